// round 15
// baseline (speedup 1.0000x reference)
#include <cuda_runtime.h>
#include <cstdint>

#define B_N   4096
#define D_DIM 1024
#define N_LAT 32768
#define TOPK  64

// frozen arithmetic: 2 k-panels of 512, fresh acc, fl(P0+P1), +b_enc, relu
#define NT 32
#define TILES_PER_CHUNK 16

#define SZ_SAE  ((size_t)B_N * D_DIM)
#define SZ_FEAT ((size_t)B_N * N_LAT)
#define SZ_TA   ((size_t)B_N * TOPK)
#define TOTAL_FULL (SZ_SAE + SZ_FEAT + SZ_TA + SZ_TA + 5)
#define TOTAL_NOFEAT (SZ_SAE + SZ_TA + SZ_TA + 5)

__device__ float g_top_val[B_N * TOPK];
__device__ int   g_top_idx[B_N * TOPK];
__device__ float g_colsum[D_DIM];
__device__ float g_acc[4];
__device__ float g_xc[(size_t)B_N * D_DIM];
__device__ float g_feat_fallback[(size_t)B_N * N_LAT];

#define FMA2(c,a,b) asm("fma.rn.f32x2 %0, %1, %2, %3;" : "=l"(c) : "l"(a), "l"(b), "l"(c))
#define ADD2(c,a,b) asm("add.rn.f32x2 %0, %1, %2;"     : "=l"(c) : "l"(a), "l"(b))
#define PAIR(d,f)   asm("mov.b64 %0, {%1, %1};"        : "=l"(d) : "r"(__float_as_uint(f)))

__device__ __forceinline__ float f2lo(unsigned long long v) { return __uint_as_float((unsigned)v); }
__device__ __forceinline__ float f2hi(unsigned long long v) { return __uint_as_float((unsigned)(v >> 32)); }
__device__ __forceinline__ unsigned long long packf2(float lo, float hi) {
    return ((unsigned long long)__float_as_uint(hi) << 32) | __float_as_uint(lo);
}

// ============================================================
__global__ void init_kernel() {
    int i = blockIdx.x * 256 + threadIdx.x;
    if (i < D_DIM) g_colsum[i] = 0.0f;
    if (i < 4) g_acc[i] = 0.0f;
}

// fused: xc = x - b_dec, column sums, sum x^2. grid (4,16), 256 thr
__global__ void xc_colstats_kernel(const float* __restrict__ X, const float* __restrict__ bdec) {
    __shared__ float redq[256];
    int c  = blockIdx.x * 256 + threadIdx.x;
    int r0 = blockIdx.y * 256;
    float bd = bdec[c];
    float s = 0.f, q = 0.f;
    #pragma unroll 4
    for (int n = r0; n < r0 + 256; n++) {
        float v = X[(size_t)n * D_DIM + c];
        s += v;
        q += v * v;
        g_xc[(size_t)n * D_DIM + c] = v - bd;
    }
    atomicAdd(&g_colsum[c], s);
    redq[threadIdx.x] = q;
    __syncthreads();
    for (int st = 128; st > 0; st >>= 1) {
        if (threadIdx.x < st) redq[threadIdx.x] += redq[threadIdx.x + st];
        __syncthreads();
    }
    if (threadIdx.x == 0) atomicAdd(&g_acc[1], redq[0]);
}

// ============================================================
// encode GEMM (unchanged R12 winner)
// ============================================================
__global__ __launch_bounds__(512, 1)
void encode_gemm(const float* __restrict__ W,
                 const float* __restrict__ benc,
                 float* __restrict__ C)
{
    extern __shared__ char smem_raw[];
    float* As = (float*)smem_raw;
    float* Bs = (float*)(smem_raw + 65536);

    int tid = threadIdx.x;
    int tx  = tid & 15;
    int ty  = tid >> 4;
    int ty8 = ty * 8;
    int tx4 = tx * 4;
    int m0 = blockIdx.x * 256;
    int n0 = blockIdx.y * 128;

    int ar = tid >> 1;
    int ac = (tid & 1) << 4;
    int br = tid >> 2;
    int bc = (tid & 3) << 3;

    const float* aptr = g_xc + (size_t)(m0 + ar) * D_DIM + ac;
    const float* bptr = W    + (size_t)(n0 + br) * D_DIM + bc;

    float4 ra[4], rb[2];

    #pragma unroll
    for (int q = 0; q < 4; q++) ra[q] = *(const float4*)(aptr + q * 4);
    #pragma unroll
    for (int q = 0; q < 2; q++) rb[q] = *(const float4*)(bptr + q * 4);
    #pragma unroll
    for (int q = 0; q < 4; q++) {
        const float* rf = (const float*)&ra[q];
        #pragma unroll
        for (int j = 0; j < 4; j++) As[(ac + q * 4 + j) * 256 + ar] = rf[j];
    }
    #pragma unroll
    for (int q = 0; q < 2; q++) {
        const float* bf = (const float*)&rb[q];
        #pragma unroll
        for (int j = 0; j < 4; j++) Bs[(bc + q * 4 + j) * 128 + br] = bf[j];
    }
    #pragma unroll
    for (int q = 0; q < 4; q++) ra[q] = *(const float4*)(aptr + 32 + q * 4);
    #pragma unroll
    for (int q = 0; q < 2; q++) rb[q] = *(const float4*)(bptr + 32 + q * 4);
    __syncthreads();

    unsigned long long acc[8][4];
    #pragma unroll
    for (int i = 0; i < 8; i++)
        #pragma unroll
        for (int j = 0; j < 4; j++) acc[i][j] = 0ULL;

    for (int t = 0; t < NT; t++) {
        int s = t & 1;
        const float* As_s = As + s * 8192;
        const float* Bs_s = Bs + s * 4096;
        #pragma unroll
        for (int kk = 0; kk < 32; kk++) {
            float4 a03 = *(const float4*)(As_s + kk * 256 + ty8);
            float4 a47 = *(const float4*)(As_s + kk * 256 + ty8 + 4);
            ulonglong2 bl = *(const ulonglong2*)(Bs_s + kk * 128 + tx4);
            ulonglong2 bh = *(const ulonglong2*)(Bs_s + kk * 128 + 64 + tx4);
            unsigned long long a2;
            PAIR(a2, a03.x);
            FMA2(acc[0][0], a2, bl.x); FMA2(acc[0][1], a2, bl.y);
            FMA2(acc[0][2], a2, bh.x); FMA2(acc[0][3], a2, bh.y);
            PAIR(a2, a03.y);
            FMA2(acc[1][0], a2, bl.x); FMA2(acc[1][1], a2, bl.y);
            FMA2(acc[1][2], a2, bh.x); FMA2(acc[1][3], a2, bh.y);
            PAIR(a2, a03.z);
            FMA2(acc[2][0], a2, bl.x); FMA2(acc[2][1], a2, bl.y);
            FMA2(acc[2][2], a2, bh.x); FMA2(acc[2][3], a2, bh.y);
            PAIR(a2, a03.w);
            FMA2(acc[3][0], a2, bl.x); FMA2(acc[3][1], a2, bl.y);
            FMA2(acc[3][2], a2, bh.x); FMA2(acc[3][3], a2, bh.y);
            PAIR(a2, a47.x);
            FMA2(acc[4][0], a2, bl.x); FMA2(acc[4][1], a2, bl.y);
            FMA2(acc[4][2], a2, bh.x); FMA2(acc[4][3], a2, bh.y);
            PAIR(a2, a47.y);
            FMA2(acc[5][0], a2, bl.x); FMA2(acc[5][1], a2, bl.y);
            FMA2(acc[5][2], a2, bh.x); FMA2(acc[5][3], a2, bh.y);
            PAIR(a2, a47.z);
            FMA2(acc[6][0], a2, bl.x); FMA2(acc[6][1], a2, bl.y);
            FMA2(acc[6][2], a2, bh.x); FMA2(acc[6][3], a2, bh.y);
            PAIR(a2, a47.w);
            FMA2(acc[7][0], a2, bl.x); FMA2(acc[7][1], a2, bl.y);
            FMA2(acc[7][2], a2, bh.x); FMA2(acc[7][3], a2, bh.y);
        }

        if (t == TILES_PER_CHUNK - 1) {
            #pragma unroll
            for (int i = 0; i < 8; i++) {
                size_t row = (size_t)(m0 + ty8 + i);
                float4 p0, p1;
                p0.x = f2lo(acc[i][0]); p0.y = f2hi(acc[i][0]);
                p0.z = f2lo(acc[i][1]); p0.w = f2hi(acc[i][1]);
                p1.x = f2lo(acc[i][2]); p1.y = f2hi(acc[i][2]);
                p1.z = f2lo(acc[i][3]); p1.w = f2hi(acc[i][3]);
                *(float4*)(C + row * N_LAT + n0 + tx4)      = p0;
                *(float4*)(C + row * N_LAT + n0 + 64 + tx4) = p1;
                #pragma unroll
                for (int j = 0; j < 4; j++) acc[i][j] = 0ULL;
            }
        }

        if (t < NT - 1) {
            int sn = (t + 1) & 1;
            float* As_n = As + sn * 8192;
            float* Bs_n = Bs + sn * 4096;
            #pragma unroll
            for (int q = 0; q < 4; q++) {
                const float* rf = (const float*)&ra[q];
                #pragma unroll
                for (int j = 0; j < 4; j++) As_n[(ac + q * 4 + j) * 256 + ar] = rf[j];
            }
            #pragma unroll
            for (int q = 0; q < 2; q++) {
                const float* bf = (const float*)&rb[q];
                #pragma unroll
                for (int j = 0; j < 4; j++) Bs_n[(bc + q * 4 + j) * 128 + br] = bf[j];
            }
            if (t < NT - 2) {
                #pragma unroll
                for (int q = 0; q < 4; q++) ra[q] = *(const float4*)(aptr + (t + 2) * 32 + q * 4);
                #pragma unroll
                for (int q = 0; q < 2; q++) rb[q] = *(const float4*)(bptr + (t + 2) * 32 + q * 4);
            }
        }
        __syncthreads();
    }

    float4 bev0 = *(const float4*)(benc + n0 + tx4);
    float4 bev1 = *(const float4*)(benc + n0 + 64 + tx4);
    #pragma unroll
    for (int i = 0; i < 8; i++) {
        size_t row = (size_t)(m0 + ty8 + i);
        float4 p0 = *(const float4*)(C + row * N_LAT + n0 + tx4);
        float4 p1 = *(const float4*)(C + row * N_LAT + n0 + 64 + tx4);
        unsigned long long s0, s1, s2, s3;
        s0 = packf2(p0.x, p0.y); s1 = packf2(p0.z, p0.w);
        s2 = packf2(p1.x, p1.y); s3 = packf2(p1.z, p1.w);
        ADD2(s0, s0, acc[i][0]);
        ADD2(s1, s1, acc[i][1]);
        ADD2(s2, s2, acc[i][2]);
        ADD2(s3, s3, acc[i][3]);
        float4 o0, o1;
        o0.x = fmaxf(f2lo(s0) + bev0.x, 0.f);
        o0.y = fmaxf(f2hi(s0) + bev0.y, 0.f);
        o0.z = fmaxf(f2lo(s1) + bev0.z, 0.f);
        o0.w = fmaxf(f2hi(s1) + bev0.w, 0.f);
        o1.x = fmaxf(f2lo(s2) + bev1.x, 0.f);
        o1.y = fmaxf(f2hi(s2) + bev1.y, 0.f);
        o1.z = fmaxf(f2lo(s3) + bev1.z, 0.f);
        o1.w = fmaxf(f2hi(s3) + bev1.w, 0.f);
        *(float4*)(C + row * N_LAT + n0 + tx4)      = o0;
        *(float4*)(C + row * N_LAT + n0 + 64 + tx4) = o1;
    }
}

// ============================================================
// top-k: sampled-threshold prescreen + exact radix on candidate list.
// Fallback to full radix (gmem) if prescreen under/overflows.
// Exact jax.lax.top_k semantics (desc value, asc index on ties).
// ============================================================
#define CAP_B 4096
#define CAP_C 1024
#define CAP_D 512
#define TOPK_SMEM ((2048 + 2*CAP_B + 2*CAP_C + 2*CAP_D) * 4)

__device__ __forceinline__ void select_bin(uint32_t* hist, int nbins, int Kr,
                                           int* csum, int* s_b, int* s_kr, int tid)
{
    int nch = nbins >> 3;
    if (tid < nch) {
        int s = 0;
        #pragma unroll
        for (int j = 0; j < 8; j++) s += (int)hist[tid * 8 + j];
        csum[tid] = s;
    }
    __syncthreads();
    if (tid == 0) {
        int acc = 0, c = nch - 1;
        for (; c > 0; c--) {
            if (acc + csum[c] >= Kr) break;
            acc += csum[c];
        }
        int b = c * 8 + 7;
        for (; b > c * 8; b--) {
            int h = (int)hist[b];
            if (acc + h >= Kr) break;
            acc += h;
        }
        *s_b = b;
        *s_kr = Kr - acc;
    }
    __syncthreads();
}

__global__ void topk_kernel(const float* __restrict__ feat,
                            float* __restrict__ p_ta, float* __restrict__ p_ti)
{
    extern __shared__ uint32_t dyn[];
    uint32_t* hist = dyn;                  // 2048
    uint32_t* Bu = hist + 2048;            // CAP_B
    uint32_t* Bi = Bu + CAP_B;
    uint32_t* Cu = Bi + CAP_B;             // CAP_C
    uint32_t* Ci = Cu + CAP_C;
    uint32_t* Du = Ci + CAP_C;             // CAP_D
    uint32_t* Di = Du + CAP_D;

    __shared__ int   csum[256];
    __shared__ int   red[256];
    __shared__ float pv[64];
    __shared__ int   pi[64];
    __shared__ int   listA[64];
    __shared__ int   tiesel[64];
    __shared__ int   s_b, s_kr, s_cntA, s_cntB, s_cntC, s_cntD, s_last, s_bsel;

    int tid = threadIdx.x;
    int row = blockIdx.x;
    const uint32_t* sf = (const uint32_t*)(feat + (size_t)row * N_LAT);

    for (int i = tid; i < 2048; i += 256) hist[i] = 0;
    if (tid == 0) { s_cntA = 0; s_cntB = 0; s_cntC = 0; s_cntD = 0; }
    __syncthreads();

    // ---- sample pass: 1024 strided values -> coarse hist ----
    #pragma unroll
    for (int j = 0; j < 4; j++) {
        uint32_t v = sf[(tid + 256 * j) * 32];
        if (v) atomicAdd(&hist[v >> 21], 1u);
    }
    __syncthreads();
    if (tid == 0) {
        int acc = 0, c = 2047;
        for (; c > 0; c--) {
            acc += (int)hist[c];
            if (acc >= 12) break;
        }
        s_bsel = c;
    }
    __syncthreads();
    uint32_t bsel = (uint32_t)s_bsel;

    // ---- collect pass: all u with (u>>21) >= bsel ----
    for (int i = tid; i < N_LAT / 4; i += 256) {
        uint4 u = ((const uint4*)sf)[i];
        uint32_t uv[4] = {u.x, u.y, u.z, u.w};
        #pragma unroll
        for (int e = 0; e < 4; e++) {
            if ((uv[e] >> 21) >= bsel) {
                int p = atomicAdd(&s_cntB, 1);
                if (p < CAP_B) { Bu[p] = uv[e]; Bi[p] = i * 4 + e; }
            }
        }
    }
    __syncthreads();
    int cB = s_cntB;
    bool fb = (cB < TOPK || cB > CAP_B);
    int b0, K1, b1, K2, b2, Need;
    uint32_t T;
    int cC, cD;

    if (!fb) {
        // ======== common path: exact radix on candidate list ========
        for (int i = tid; i < 2048; i += 256) hist[i] = 0;
        __syncthreads();
        for (int j = tid; j < cB; j += 256) atomicAdd(&hist[Bu[j] >> 21], 1u);
        __syncthreads();
        select_bin(hist, 2048, TOPK, csum, &s_b, &s_kr, tid);
        b0 = s_b; K1 = s_kr;

        for (int i = tid; i < 2048; i += 256) hist[i] = 0;
        __syncthreads();
        for (int j = tid; j < cB; j += 256) {
            uint32_t v = Bu[j];
            int b = (int)(v >> 21);
            if (b > b0) {
                int p = atomicAdd(&s_cntA, 1);
                if (p < 64) listA[p] = (int)Bi[j];
            } else if (b == b0) {
                int p = atomicAdd(&s_cntC, 1);
                if (p < CAP_C) { Cu[p] = v; Ci[p] = Bi[j]; }
                atomicAdd(&hist[(v >> 10) & 0x7FF], 1u);
            }
        }
        __syncthreads();
        cC = s_cntC;
        select_bin(hist, 2048, K1, csum, &s_b, &s_kr, tid);
        b1 = s_b; K2 = s_kr;

        for (int i = tid; i < 1024; i += 256) hist[i] = 0;
        __syncthreads();
        if (cC <= CAP_C) {
            for (int j = tid; j < cC; j += 256) {
                uint32_t v = Cu[j];
                int mid = (int)((v >> 10) & 0x7FF);
                if (mid > b1) {
                    int p = atomicAdd(&s_cntA, 1);
                    if (p < 64) listA[p] = (int)Ci[j];
                } else if (mid == b1) {
                    int p = atomicAdd(&s_cntD, 1);
                    if (p < CAP_D) { Du[p] = v; Di[p] = Ci[j]; }
                    atomicAdd(&hist[v & 0x3FF], 1u);
                }
            }
        } else {
            for (int j = tid; j < cB; j += 256) {
                uint32_t v = Bu[j];
                if ((int)(v >> 21) != b0) continue;
                int mid = (int)((v >> 10) & 0x7FF);
                if (mid > b1) {
                    int p = atomicAdd(&s_cntA, 1);
                    if (p < 64) listA[p] = (int)Bi[j];
                } else if (mid == b1) {
                    int p = atomicAdd(&s_cntD, 1);
                    if (p < CAP_D) { Du[p] = v; Di[p] = Bi[j]; }
                    atomicAdd(&hist[v & 0x3FF], 1u);
                }
            }
        }
        __syncthreads();
        cD = s_cntD;
        select_bin(hist, 1024, K2, csum, &s_b, &s_kr, tid);
        b2 = s_b; Need = s_kr;
        T = ((uint32_t)b0 << 21) | ((uint32_t)b1 << 10) | (uint32_t)b2;

        // low > b2 -> listA
        if (cD <= CAP_D) {
            for (int j = tid; j < cD; j += 256) {
                uint32_t v = Du[j];
                if ((int)(v & 0x3FF) > b2) {
                    int p = atomicAdd(&s_cntA, 1);
                    if (p < 64) listA[p] = (int)Di[j];
                }
            }
        } else {
            uint32_t pref = ((uint32_t)b0 << 11) | (uint32_t)b1;
            for (int j = tid; j < cB; j += 256) {
                uint32_t v = Bu[j];
                if ((v >> 10) != pref) continue;
                if ((int)(v & 0x3FF) > b2) {
                    int p = atomicAdd(&s_cntA, 1);
                    if (p < 64) listA[p] = (int)Bi[j];
                }
            }
        }
        __syncthreads();

        // ties: `Need` smallest indices with u == T (all in listB)
        int last = -1;
        for (int s = 0; s < Need; s++) {
            int loc = 0x7FFFFFFF;
            if (cD <= CAP_D) {
                for (int j = tid; j < cD; j += 256) {
                    if (Du[j] == T) {
                        int ix = (int)Di[j];
                        if (ix > last && ix < loc) loc = ix;
                    }
                }
            } else {
                for (int j = tid; j < cB; j += 256) {
                    if (Bu[j] == T) {
                        int ix = (int)Bi[j];
                        if (ix > last && ix < loc) loc = ix;
                    }
                }
            }
            red[tid] = loc;
            __syncthreads();
            for (int st = 128; st > 0; st >>= 1) {
                if (tid < st) red[tid] = min(red[tid], red[tid + st]);
                __syncthreads();
            }
            if (tid == 0) { tiesel[s] = red[0]; s_last = red[0]; }
            __syncthreads();
            last = s_last;
        }
    } else {
        // ======== fallback: full radix over gmem (R14 path) ========
        if (tid == 0) { s_cntA = 0; s_cntB = 0; s_cntC = 0; s_cntD = 0; }
        for (int i = tid; i < 2048; i += 256) hist[i] = 0;
        __syncthreads();
        int zloc = 0;
        for (int i = tid; i < N_LAT; i += 256) {
            uint32_t v = sf[i];
            if (v) atomicAdd(&hist[v >> 21], 1u); else zloc++;
        }
        if (zloc) atomicAdd(&hist[0], (uint32_t)zloc);
        __syncthreads();
        select_bin(hist, 2048, TOPK, csum, &s_b, &s_kr, tid);
        b0 = s_b; K1 = s_kr;

        for (int i = tid; i < 2048; i += 256) hist[i] = 0;
        __syncthreads();
        for (int i = tid; i < N_LAT; i += 256) {
            uint32_t v = sf[i];
            int b = (int)(v >> 21);
            if (b > b0) {
                int p = atomicAdd(&s_cntA, 1);
                if (p < 64) listA[p] = i;
            } else if (b == b0) {
                int p = atomicAdd(&s_cntB, 1);
                if (p < CAP_B) { Bu[p] = v; Bi[p] = (uint32_t)i; }
                atomicAdd(&hist[(v >> 10) & 0x7FF], 1u);
            }
        }
        __syncthreads();
        cB = s_cntB;
        select_bin(hist, 2048, K1, csum, &s_b, &s_kr, tid);
        b1 = s_b; K2 = s_kr;

        for (int i = tid; i < 1024; i += 256) hist[i] = 0;
        __syncthreads();
        if (cB <= CAP_B) {
            for (int j = tid; j < cB; j += 256) {
                uint32_t v = Bu[j];
                int mid = (int)((v >> 10) & 0x7FF);
                if (mid > b1) {
                    int p = atomicAdd(&s_cntA, 1);
                    if (p < 64) listA[p] = (int)Bi[j];
                } else if (mid == b1) {
                    int p = atomicAdd(&s_cntC, 1);
                    if (p < CAP_C) { Cu[p] = v; Ci[p] = Bi[j]; }
                    atomicAdd(&hist[v & 0x3FF], 1u);
                }
            }
        } else {
            for (int i = tid; i < N_LAT; i += 256) {
                uint32_t v = sf[i];
                if ((int)(v >> 21) != b0) continue;
                int mid = (int)((v >> 10) & 0x7FF);
                if (mid > b1) {
                    int p = atomicAdd(&s_cntA, 1);
                    if (p < 64) listA[p] = i;
                } else if (mid == b1) {
                    int p = atomicAdd(&s_cntC, 1);
                    if (p < CAP_C) { Cu[p] = v; Ci[p] = (uint32_t)i; }
                    atomicAdd(&hist[v & 0x3FF], 1u);
                }
            }
        }
        __syncthreads();
        cC = s_cntC;
        select_bin(hist, 1024, K2, csum, &s_b, &s_kr, tid);
        b2 = s_b; Need = s_kr;
        T = ((uint32_t)b0 << 21) | ((uint32_t)b1 << 10) | (uint32_t)b2;

        if (cC <= CAP_C) {
            for (int j = tid; j < cC; j += 256) {
                uint32_t v = Cu[j];
                if ((int)(v & 0x3FF) > b2) {
                    int p = atomicAdd(&s_cntA, 1);
                    if (p < 64) listA[p] = (int)Ci[j];
                }
            }
        } else {
            uint32_t pref = ((uint32_t)b0 << 11) | (uint32_t)b1;
            for (int i = tid; i < N_LAT; i += 256) {
                uint32_t v = sf[i];
                if ((v >> 10) != pref) continue;
                if ((int)(v & 0x3FF) > b2) {
                    int p = atomicAdd(&s_cntA, 1);
                    if (p < 64) listA[p] = i;
                }
            }
        }
        __syncthreads();

        int last = -1;
        for (int s = 0; s < Need; s++) {
            int loc = 0x7FFFFFFF;
            if (cC <= CAP_C) {
                for (int j = tid; j < cC; j += 256) {
                    if (Cu[j] == T) {
                        int ix = (int)Ci[j];
                        if (ix > last && ix < loc) loc = ix;
                    }
                }
            } else {
                for (int i = tid; i < N_LAT; i += 256) {
                    if (sf[i] == T && i > last && i < loc) loc = i;
                }
            }
            red[tid] = loc;
            __syncthreads();
            for (int st = 128; st > 0; st >>= 1) {
                if (tid < st) red[tid] = min(red[tid], red[tid + st]);
                __syncthreads();
            }
            if (tid == 0) { tiesel[s] = red[0]; s_last = red[0]; }
            __syncthreads();
            last = s_last;
        }
    }

    int cA = s_cntA;

    // ---- rank + write (descending value, ascending index on ties) ----
    if (tid < 64) {
        float v; int ix;
        if (tid < cA) { ix = listA[tid]; v = __uint_as_float(sf[ix]); }
        else          { ix = tiesel[tid - cA]; v = __uint_as_float(T); }
        pv[tid] = v; pi[tid] = ix;
    }
    __syncthreads();
    if (tid < 64) {
        float v = pv[tid]; int ix = pi[tid];
        int rank = 0;
        #pragma unroll 8
        for (int j = 0; j < 64; j++) {
            float vj = pv[j]; int ij = pi[j];
            if (vj > v || (vj == v && ij < ix)) rank++;
        }
        size_t o = (size_t)row * TOPK + rank;
        g_top_val[o] = v;
        g_top_idx[o] = ix;
        if (p_ta) p_ta[o] = v;
        if (p_ti) p_ti[o] = (float)ix;
    }
}

// ============================================================
__global__ void decode_kernel(const float* __restrict__ X,
                              const float* __restrict__ Wd,
                              const float* __restrict__ bdec,
                              float* __restrict__ sae)
{
    __shared__ float sval[64];
    __shared__ int   sidx[64];
    __shared__ float red[256];
    int tid = threadIdx.x, row = blockIdx.x;
    if (tid < 64) {
        sval[tid] = g_top_val[row * TOPK + tid];
        sidx[tid] = g_top_idx[row * TOPK + tid];
    }
    __syncthreads();
    int d0 = tid * 4;
    float4 acc = *(const float4*)(bdec + d0);
    #pragma unroll 4
    for (int k = 0; k < TOPK; k++) {
        float a = sval[k];
        float4 w = *(const float4*)(Wd + (size_t)sidx[k] * D_DIM + d0);
        acc.x += a * w.x; acc.y += a * w.y; acc.z += a * w.z; acc.w += a * w.w;
    }
    size_t o = (size_t)row * D_DIM + d0;
    if (sae) *(float4*)(sae + o) = acc;
    float4 xv = *(const float4*)(X + o);
    float ex = acc.x - xv.x, ey = acc.y - xv.y, ez = acc.z - xv.z, ew = acc.w - xv.w;
    red[tid] = ex * ex + ey * ey + ez * ez + ew * ew;
    __syncthreads();
    for (int st = 128; st > 0; st >>= 1) {
        if (tid < st) red[tid] += red[tid + st];
        __syncthreads();
    }
    if (tid == 0) atomicAdd(&g_acc[0], red[0]);
}

// ============================================================
__global__ void finalize_kernel(float* __restrict__ p_sc) {
    __shared__ float red[256];
    int tid = threadIdx.x;
    float s = 0.f;
    for (int i = tid; i < D_DIM; i += 256) {
        float cs = g_colsum[i];
        s += cs * cs;
    }
    red[tid] = s;
    __syncthreads();
    for (int st = 128; st > 0; st >>= 1) {
        if (tid < st) red[tid] += red[tid + st];
        __syncthreads();
    }
    if (tid == 0) {
        float TV  = g_acc[1] - red[0] / (float)B_N;
        float SSE = g_acc[0];
        p_sc[0] = SSE / TV;
        p_sc[1] = 0.f;
        p_sc[2] = 0.f;
        p_sc[3] = 0.f;
        p_sc[4] = SSE / (float)B_N;
    }
}

// ============================================================
extern "C" void kernel_launch(void* const* d_in, const int* in_sizes, int n_in,
                              void* d_out, int out_size)
{
    const float *x = nullptr, *We = nullptr, *be = nullptr, *Wd = nullptr, *bd = nullptr;
    int big_seen = 0;
    for (int i = 0; i < n_in; i++) {
        int sz = in_sizes[i];
        const float* p = (const float*)d_in[i];
        if (sz == (int)SZ_SAE)          x = p;
        else if (sz == N_LAT * D_DIM)   { if (big_seen++ == 0) We = p; else Wd = p; }
        else if (sz == N_LAT)           be = p;
        else if (sz == D_DIM)           bd = p;
    }

    float* out = (float*)d_out;
    float *p_sae = nullptr, *p_feat = nullptr, *p_ta = nullptr, *p_ti = nullptr, *p_sc = nullptr;

    if ((size_t)out_size == TOTAL_FULL) {
        p_sae  = out;
        p_feat = out + SZ_SAE;
        p_ta   = out + SZ_SAE + SZ_FEAT;
        p_ti   = p_ta + SZ_TA;
        p_sc   = p_ti + SZ_TA;
    } else if ((size_t)out_size == TOTAL_NOFEAT) {
        p_sae = out;
        p_ta  = out + SZ_SAE;
        p_ti  = p_ta + SZ_TA;
        p_sc  = p_ti + SZ_TA;
    } else {
        p_sae = out;
    }

    if (!p_feat) {
        void* fp = nullptr;
        cudaGetSymbolAddress(&fp, g_feat_fallback);
        p_feat = (float*)fp;
    }

    init_kernel<<<4, 256>>>();
    xc_colstats_kernel<<<dim3(4, 16), 256>>>(x, bd);
    cudaFuncSetAttribute(encode_gemm, cudaFuncAttributeMaxDynamicSharedMemorySize, 98304);
    encode_gemm<<<dim3(B_N / 256, N_LAT / 128), 512, 98304>>>(We, be, p_feat);
    cudaFuncSetAttribute(topk_kernel, cudaFuncAttributeMaxDynamicSharedMemorySize, TOPK_SMEM);
    topk_kernel<<<B_N, 256, TOPK_SMEM>>>(p_feat, p_ta, p_ti);
    decode_kernel<<<B_N, 256>>>(x, Wd, bd, p_sae);
    if (p_sc) finalize_kernel<<<1, 256>>>(p_sc);
}

// round 16
// speedup vs baseline: 1.0498x; 1.0498x over previous
#include <cuda_runtime.h>
#include <cstdint>

#define B_N   4096
#define D_DIM 1024
#define N_LAT 32768
#define TOPK  64

// frozen arithmetic: 2 k-panels of 512, fresh acc, fl(P0+P1), +b_enc, relu
#define NT 32
#define TILES_PER_CHUNK 16

#define SZ_SAE  ((size_t)B_N * D_DIM)
#define SZ_FEAT ((size_t)B_N * N_LAT)
#define SZ_TA   ((size_t)B_N * TOPK)
#define TOTAL_FULL (SZ_SAE + SZ_FEAT + SZ_TA + SZ_TA + 5)
#define TOTAL_NOFEAT (SZ_SAE + SZ_TA + SZ_TA + 5)

__device__ float g_top_val[B_N * TOPK];
__device__ int   g_top_idx[B_N * TOPK];
__device__ float g_colsum[D_DIM];
__device__ float g_acc[4];
__device__ float g_xc[(size_t)B_N * D_DIM];
__device__ float g_feat_fallback[(size_t)B_N * N_LAT];

#define FMA2(c,a,b) asm("fma.rn.f32x2 %0, %1, %2, %3;" : "=l"(c) : "l"(a), "l"(b), "l"(c))
#define ADD2(c,a,b) asm("add.rn.f32x2 %0, %1, %2;"     : "=l"(c) : "l"(a), "l"(b))
#define PAIR(d,f)   asm("mov.b64 %0, {%1, %1};"        : "=l"(d) : "r"(__float_as_uint(f)))

__device__ __forceinline__ float f2lo(unsigned long long v) { return __uint_as_float((unsigned)v); }
__device__ __forceinline__ float f2hi(unsigned long long v) { return __uint_as_float((unsigned)(v >> 32)); }
__device__ __forceinline__ unsigned long long packf2(float lo, float hi) {
    return ((unsigned long long)__float_as_uint(hi) << 32) | __float_as_uint(lo);
}

// ============================================================
__global__ void init_kernel() {
    int i = blockIdx.x * 256 + threadIdx.x;
    if (i < D_DIM) g_colsum[i] = 0.0f;
    if (i < 4) g_acc[i] = 0.0f;
}

// fused: xc = x - b_dec, column sums, sum x^2. grid (4,16), 256 thr
__global__ void xc_colstats_kernel(const float* __restrict__ X, const float* __restrict__ bdec) {
    __shared__ float redq[256];
    int c  = blockIdx.x * 256 + threadIdx.x;
    int r0 = blockIdx.y * 256;
    float bd = bdec[c];
    float s = 0.f, q = 0.f;
    #pragma unroll 4
    for (int n = r0; n < r0 + 256; n++) {
        float v = X[(size_t)n * D_DIM + c];
        s += v;
        q += v * v;
        g_xc[(size_t)n * D_DIM + c] = v - bd;
    }
    atomicAdd(&g_colsum[c], s);
    redq[threadIdx.x] = q;
    __syncthreads();
    for (int st = 128; st > 0; st >>= 1) {
        if (threadIdx.x < st) redq[threadIdx.x] += redq[threadIdx.x + st];
        __syncthreads();
    }
    if (threadIdx.x == 0) atomicAdd(&g_acc[1], redq[0]);
}

// ============================================================
// encode GEMM (unchanged R12 winner)
// ============================================================
__global__ __launch_bounds__(512, 1)
void encode_gemm(const float* __restrict__ W,
                 const float* __restrict__ benc,
                 float* __restrict__ C)
{
    extern __shared__ char smem_raw[];
    float* As = (float*)smem_raw;
    float* Bs = (float*)(smem_raw + 65536);

    int tid = threadIdx.x;
    int tx  = tid & 15;
    int ty  = tid >> 4;
    int ty8 = ty * 8;
    int tx4 = tx * 4;
    int m0 = blockIdx.x * 256;
    int n0 = blockIdx.y * 128;

    int ar = tid >> 1;
    int ac = (tid & 1) << 4;
    int br = tid >> 2;
    int bc = (tid & 3) << 3;

    const float* aptr = g_xc + (size_t)(m0 + ar) * D_DIM + ac;
    const float* bptr = W    + (size_t)(n0 + br) * D_DIM + bc;

    float4 ra[4], rb[2];

    #pragma unroll
    for (int q = 0; q < 4; q++) ra[q] = *(const float4*)(aptr + q * 4);
    #pragma unroll
    for (int q = 0; q < 2; q++) rb[q] = *(const float4*)(bptr + q * 4);
    #pragma unroll
    for (int q = 0; q < 4; q++) {
        const float* rf = (const float*)&ra[q];
        #pragma unroll
        for (int j = 0; j < 4; j++) As[(ac + q * 4 + j) * 256 + ar] = rf[j];
    }
    #pragma unroll
    for (int q = 0; q < 2; q++) {
        const float* bf = (const float*)&rb[q];
        #pragma unroll
        for (int j = 0; j < 4; j++) Bs[(bc + q * 4 + j) * 128 + br] = bf[j];
    }
    #pragma unroll
    for (int q = 0; q < 4; q++) ra[q] = *(const float4*)(aptr + 32 + q * 4);
    #pragma unroll
    for (int q = 0; q < 2; q++) rb[q] = *(const float4*)(bptr + 32 + q * 4);
    __syncthreads();

    unsigned long long acc[8][4];
    #pragma unroll
    for (int i = 0; i < 8; i++)
        #pragma unroll
        for (int j = 0; j < 4; j++) acc[i][j] = 0ULL;

    for (int t = 0; t < NT; t++) {
        int s = t & 1;
        const float* As_s = As + s * 8192;
        const float* Bs_s = Bs + s * 4096;
        #pragma unroll
        for (int kk = 0; kk < 32; kk++) {
            float4 a03 = *(const float4*)(As_s + kk * 256 + ty8);
            float4 a47 = *(const float4*)(As_s + kk * 256 + ty8 + 4);
            ulonglong2 bl = *(const ulonglong2*)(Bs_s + kk * 128 + tx4);
            ulonglong2 bh = *(const ulonglong2*)(Bs_s + kk * 128 + 64 + tx4);
            unsigned long long a2;
            PAIR(a2, a03.x);
            FMA2(acc[0][0], a2, bl.x); FMA2(acc[0][1], a2, bl.y);
            FMA2(acc[0][2], a2, bh.x); FMA2(acc[0][3], a2, bh.y);
            PAIR(a2, a03.y);
            FMA2(acc[1][0], a2, bl.x); FMA2(acc[1][1], a2, bl.y);
            FMA2(acc[1][2], a2, bh.x); FMA2(acc[1][3], a2, bh.y);
            PAIR(a2, a03.z);
            FMA2(acc[2][0], a2, bl.x); FMA2(acc[2][1], a2, bl.y);
            FMA2(acc[2][2], a2, bh.x); FMA2(acc[2][3], a2, bh.y);
            PAIR(a2, a03.w);
            FMA2(acc[3][0], a2, bl.x); FMA2(acc[3][1], a2, bl.y);
            FMA2(acc[3][2], a2, bh.x); FMA2(acc[3][3], a2, bh.y);
            PAIR(a2, a47.x);
            FMA2(acc[4][0], a2, bl.x); FMA2(acc[4][1], a2, bl.y);
            FMA2(acc[4][2], a2, bh.x); FMA2(acc[4][3], a2, bh.y);
            PAIR(a2, a47.y);
            FMA2(acc[5][0], a2, bl.x); FMA2(acc[5][1], a2, bl.y);
            FMA2(acc[5][2], a2, bh.x); FMA2(acc[5][3], a2, bh.y);
            PAIR(a2, a47.z);
            FMA2(acc[6][0], a2, bl.x); FMA2(acc[6][1], a2, bl.y);
            FMA2(acc[6][2], a2, bh.x); FMA2(acc[6][3], a2, bh.y);
            PAIR(a2, a47.w);
            FMA2(acc[7][0], a2, bl.x); FMA2(acc[7][1], a2, bl.y);
            FMA2(acc[7][2], a2, bh.x); FMA2(acc[7][3], a2, bh.y);
        }

        if (t == TILES_PER_CHUNK - 1) {
            #pragma unroll
            for (int i = 0; i < 8; i++) {
                size_t row = (size_t)(m0 + ty8 + i);
                float4 p0, p1;
                p0.x = f2lo(acc[i][0]); p0.y = f2hi(acc[i][0]);
                p0.z = f2lo(acc[i][1]); p0.w = f2hi(acc[i][1]);
                p1.x = f2lo(acc[i][2]); p1.y = f2hi(acc[i][2]);
                p1.z = f2lo(acc[i][3]); p1.w = f2hi(acc[i][3]);
                *(float4*)(C + row * N_LAT + n0 + tx4)      = p0;
                *(float4*)(C + row * N_LAT + n0 + 64 + tx4) = p1;
                #pragma unroll
                for (int j = 0; j < 4; j++) acc[i][j] = 0ULL;
            }
        }

        if (t < NT - 1) {
            int sn = (t + 1) & 1;
            float* As_n = As + sn * 8192;
            float* Bs_n = Bs + sn * 4096;
            #pragma unroll
            for (int q = 0; q < 4; q++) {
                const float* rf = (const float*)&ra[q];
                #pragma unroll
                for (int j = 0; j < 4; j++) As_n[(ac + q * 4 + j) * 256 + ar] = rf[j];
            }
            #pragma unroll
            for (int q = 0; q < 2; q++) {
                const float* bf = (const float*)&rb[q];
                #pragma unroll
                for (int j = 0; j < 4; j++) Bs_n[(bc + q * 4 + j) * 128 + br] = bf[j];
            }
            if (t < NT - 2) {
                #pragma unroll
                for (int q = 0; q < 4; q++) ra[q] = *(const float4*)(aptr + (t + 2) * 32 + q * 4);
                #pragma unroll
                for (int q = 0; q < 2; q++) rb[q] = *(const float4*)(bptr + (t + 2) * 32 + q * 4);
            }
        }
        __syncthreads();
    }

    float4 bev0 = *(const float4*)(benc + n0 + tx4);
    float4 bev1 = *(const float4*)(benc + n0 + 64 + tx4);
    #pragma unroll
    for (int i = 0; i < 8; i++) {
        size_t row = (size_t)(m0 + ty8 + i);
        float4 p0 = *(const float4*)(C + row * N_LAT + n0 + tx4);
        float4 p1 = *(const float4*)(C + row * N_LAT + n0 + 64 + tx4);
        unsigned long long s0, s1, s2, s3;
        s0 = packf2(p0.x, p0.y); s1 = packf2(p0.z, p0.w);
        s2 = packf2(p1.x, p1.y); s3 = packf2(p1.z, p1.w);
        ADD2(s0, s0, acc[i][0]);
        ADD2(s1, s1, acc[i][1]);
        ADD2(s2, s2, acc[i][2]);
        ADD2(s3, s3, acc[i][3]);
        float4 o0, o1;
        o0.x = fmaxf(f2lo(s0) + bev0.x, 0.f);
        o0.y = fmaxf(f2hi(s0) + bev0.y, 0.f);
        o0.z = fmaxf(f2lo(s1) + bev0.z, 0.f);
        o0.w = fmaxf(f2hi(s1) + bev0.w, 0.f);
        o1.x = fmaxf(f2lo(s2) + bev1.x, 0.f);
        o1.y = fmaxf(f2hi(s2) + bev1.y, 0.f);
        o1.z = fmaxf(f2lo(s3) + bev1.z, 0.f);
        o1.w = fmaxf(f2hi(s3) + bev1.w, 0.f);
        *(float4*)(C + row * N_LAT + n0 + tx4)      = o0;
        *(float4*)(C + row * N_LAT + n0 + 64 + tx4) = o1;
    }
}

// ============================================================
// top-k: sampled-threshold prescreen + exact radix on candidate list.
// Threshold selection uses CHUNKED select_bin (fixes R15's ~1500-iter
// serial scan). Fallback to full radix if prescreen under/overflows.
// Exact jax.lax.top_k semantics (desc value, asc index on ties).
// ============================================================
#define CAP_B 4096
#define CAP_C 1024
#define CAP_D 512
#define TOPK_SMEM ((2048 + 2*CAP_B + 2*CAP_C + 2*CAP_D) * 4)

__device__ __forceinline__ void select_bin(uint32_t* hist, int nbins, int Kr,
                                           int* csum, int* s_b, int* s_kr, int tid)
{
    int nch = nbins >> 3;
    if (tid < nch) {
        int s = 0;
        #pragma unroll
        for (int j = 0; j < 8; j++) s += (int)hist[tid * 8 + j];
        csum[tid] = s;
    }
    __syncthreads();
    if (tid == 0) {
        int acc = 0, c = nch - 1;
        for (; c > 0; c--) {
            if (acc + csum[c] >= Kr) break;
            acc += csum[c];
        }
        int b = c * 8 + 7;
        for (; b > c * 8; b--) {
            int h = (int)hist[b];
            if (acc + h >= Kr) break;
            acc += h;
        }
        *s_b = b;
        *s_kr = Kr - acc;
    }
    __syncthreads();
}

__global__ void topk_kernel(const float* __restrict__ feat,
                            float* __restrict__ p_ta, float* __restrict__ p_ti)
{
    extern __shared__ uint32_t dyn[];
    uint32_t* hist = dyn;                  // 2048
    uint32_t* Bu = hist + 2048;            // CAP_B
    uint32_t* Bi = Bu + CAP_B;
    uint32_t* Cu = Bi + CAP_B;             // CAP_C
    uint32_t* Ci = Cu + CAP_C;
    uint32_t* Du = Ci + CAP_C;             // CAP_D
    uint32_t* Di = Du + CAP_D;

    __shared__ int   csum[256];
    __shared__ int   red[256];
    __shared__ float pv[64];
    __shared__ int   pi[64];
    __shared__ int   listA[64];
    __shared__ int   tiesel[64];
    __shared__ int   s_b, s_kr, s_cntA, s_cntB, s_cntC, s_cntD, s_last;

    int tid = threadIdx.x;
    int row = blockIdx.x;
    const uint32_t* sf = (const uint32_t*)(feat + (size_t)row * N_LAT);

    for (int i = tid; i < 2048; i += 256) hist[i] = 0;
    if (tid == 0) { s_cntA = 0; s_cntB = 0; s_cntC = 0; s_cntD = 0; }
    __syncthreads();

    // ---- sample pass: 1024 strided values -> coarse hist ----
    #pragma unroll
    for (int j = 0; j < 4; j++) {
        uint32_t v = sf[(tid + 256 * j) * 32];
        if (v) atomicAdd(&hist[v >> 21], 1u);
    }
    __syncthreads();
    // chunked threshold selection: largest bin with sample suffix-count >= 12
    select_bin(hist, 2048, 12, csum, &s_b, &s_kr, tid);
    uint32_t bsel = (uint32_t)s_b;

    // ---- collect pass: all u with (u>>21) >= bsel ----
    for (int i = tid; i < N_LAT / 4; i += 256) {
        uint4 u = ((const uint4*)sf)[i];
        uint32_t uv[4] = {u.x, u.y, u.z, u.w};
        #pragma unroll
        for (int e = 0; e < 4; e++) {
            if ((uv[e] >> 21) >= bsel) {
                int p = atomicAdd(&s_cntB, 1);
                if (p < CAP_B) { Bu[p] = uv[e]; Bi[p] = i * 4 + e; }
            }
        }
    }
    __syncthreads();
    int cB = s_cntB;
    bool fb = (cB < TOPK || cB > CAP_B);
    int b0, K1, b1, K2, b2, Need;
    uint32_t T;
    int cC, cD;

    if (!fb) {
        // ======== common path: exact radix on candidate list ========
        for (int i = tid; i < 2048; i += 256) hist[i] = 0;
        __syncthreads();
        for (int j = tid; j < cB; j += 256) atomicAdd(&hist[Bu[j] >> 21], 1u);
        __syncthreads();
        select_bin(hist, 2048, TOPK, csum, &s_b, &s_kr, tid);
        b0 = s_b; K1 = s_kr;

        for (int i = tid; i < 2048; i += 256) hist[i] = 0;
        __syncthreads();
        for (int j = tid; j < cB; j += 256) {
            uint32_t v = Bu[j];
            int b = (int)(v >> 21);
            if (b > b0) {
                int p = atomicAdd(&s_cntA, 1);
                if (p < 64) listA[p] = (int)Bi[j];
            } else if (b == b0) {
                int p = atomicAdd(&s_cntC, 1);
                if (p < CAP_C) { Cu[p] = v; Ci[p] = Bi[j]; }
                atomicAdd(&hist[(v >> 10) & 0x7FF], 1u);
            }
        }
        __syncthreads();
        cC = s_cntC;
        select_bin(hist, 2048, K1, csum, &s_b, &s_kr, tid);
        b1 = s_b; K2 = s_kr;

        for (int i = tid; i < 1024; i += 256) hist[i] = 0;
        __syncthreads();
        if (cC <= CAP_C) {
            for (int j = tid; j < cC; j += 256) {
                uint32_t v = Cu[j];
                int mid = (int)((v >> 10) & 0x7FF);
                if (mid > b1) {
                    int p = atomicAdd(&s_cntA, 1);
                    if (p < 64) listA[p] = (int)Ci[j];
                } else if (mid == b1) {
                    int p = atomicAdd(&s_cntD, 1);
                    if (p < CAP_D) { Du[p] = v; Di[p] = Ci[j]; }
                    atomicAdd(&hist[v & 0x3FF], 1u);
                }
            }
        } else {
            for (int j = tid; j < cB; j += 256) {
                uint32_t v = Bu[j];
                if ((int)(v >> 21) != b0) continue;
                int mid = (int)((v >> 10) & 0x7FF);
                if (mid > b1) {
                    int p = atomicAdd(&s_cntA, 1);
                    if (p < 64) listA[p] = (int)Bi[j];
                } else if (mid == b1) {
                    int p = atomicAdd(&s_cntD, 1);
                    if (p < CAP_D) { Du[p] = v; Di[p] = Bi[j]; }
                    atomicAdd(&hist[v & 0x3FF], 1u);
                }
            }
        }
        __syncthreads();
        cD = s_cntD;
        select_bin(hist, 1024, K2, csum, &s_b, &s_kr, tid);
        b2 = s_b; Need = s_kr;
        T = ((uint32_t)b0 << 21) | ((uint32_t)b1 << 10) | (uint32_t)b2;

        // low > b2 -> listA
        if (cD <= CAP_D) {
            for (int j = tid; j < cD; j += 256) {
                uint32_t v = Du[j];
                if ((int)(v & 0x3FF) > b2) {
                    int p = atomicAdd(&s_cntA, 1);
                    if (p < 64) listA[p] = (int)Di[j];
                }
            }
        } else {
            uint32_t pref = ((uint32_t)b0 << 11) | (uint32_t)b1;
            for (int j = tid; j < cB; j += 256) {
                uint32_t v = Bu[j];
                if ((v >> 10) != pref) continue;
                if ((int)(v & 0x3FF) > b2) {
                    int p = atomicAdd(&s_cntA, 1);
                    if (p < 64) listA[p] = (int)Bi[j];
                }
            }
        }
        __syncthreads();

        // ties: `Need` smallest indices with u == T
        int last = -1;
        for (int s = 0; s < Need; s++) {
            int loc = 0x7FFFFFFF;
            if (cD <= CAP_D) {
                for (int j = tid; j < cD; j += 256) {
                    if (Du[j] == T) {
                        int ix = (int)Di[j];
                        if (ix > last && ix < loc) loc = ix;
                    }
                }
            } else {
                for (int j = tid; j < cB; j += 256) {
                    if (Bu[j] == T) {
                        int ix = (int)Bi[j];
                        if (ix > last && ix < loc) loc = ix;
                    }
                }
            }
            red[tid] = loc;
            __syncthreads();
            for (int st = 128; st > 0; st >>= 1) {
                if (tid < st) red[tid] = min(red[tid], red[tid + st]);
                __syncthreads();
            }
            if (tid == 0) { tiesel[s] = red[0]; s_last = red[0]; }
            __syncthreads();
            last = s_last;
        }
    } else {
        // ======== fallback: full radix over gmem ========
        if (tid == 0) { s_cntA = 0; s_cntB = 0; s_cntC = 0; s_cntD = 0; }
        for (int i = tid; i < 2048; i += 256) hist[i] = 0;
        __syncthreads();
        int zloc = 0;
        for (int i = tid; i < N_LAT; i += 256) {
            uint32_t v = sf[i];
            if (v) atomicAdd(&hist[v >> 21], 1u); else zloc++;
        }
        if (zloc) atomicAdd(&hist[0], (uint32_t)zloc);
        __syncthreads();
        select_bin(hist, 2048, TOPK, csum, &s_b, &s_kr, tid);
        b0 = s_b; K1 = s_kr;

        for (int i = tid; i < 2048; i += 256) hist[i] = 0;
        __syncthreads();
        for (int i = tid; i < N_LAT; i += 256) {
            uint32_t v = sf[i];
            int b = (int)(v >> 21);
            if (b > b0) {
                int p = atomicAdd(&s_cntA, 1);
                if (p < 64) listA[p] = i;
            } else if (b == b0) {
                int p = atomicAdd(&s_cntB, 1);
                if (p < CAP_B) { Bu[p] = v; Bi[p] = (uint32_t)i; }
                atomicAdd(&hist[(v >> 10) & 0x7FF], 1u);
            }
        }
        __syncthreads();
        cB = s_cntB;
        select_bin(hist, 2048, K1, csum, &s_b, &s_kr, tid);
        b1 = s_b; K2 = s_kr;

        for (int i = tid; i < 1024; i += 256) hist[i] = 0;
        __syncthreads();
        if (cB <= CAP_B) {
            for (int j = tid; j < cB; j += 256) {
                uint32_t v = Bu[j];
                int mid = (int)((v >> 10) & 0x7FF);
                if (mid > b1) {
                    int p = atomicAdd(&s_cntA, 1);
                    if (p < 64) listA[p] = (int)Bi[j];
                } else if (mid == b1) {
                    int p = atomicAdd(&s_cntC, 1);
                    if (p < CAP_C) { Cu[p] = v; Ci[p] = Bi[j]; }
                    atomicAdd(&hist[v & 0x3FF], 1u);
                }
            }
        } else {
            for (int i = tid; i < N_LAT; i += 256) {
                uint32_t v = sf[i];
                if ((int)(v >> 21) != b0) continue;
                int mid = (int)((v >> 10) & 0x7FF);
                if (mid > b1) {
                    int p = atomicAdd(&s_cntA, 1);
                    if (p < 64) listA[p] = i;
                } else if (mid == b1) {
                    int p = atomicAdd(&s_cntC, 1);
                    if (p < CAP_C) { Cu[p] = v; Ci[p] = (uint32_t)i; }
                    atomicAdd(&hist[v & 0x3FF], 1u);
                }
            }
        }
        __syncthreads();
        cC = s_cntC;
        select_bin(hist, 1024, K2, csum, &s_b, &s_kr, tid);
        b2 = s_b; Need = s_kr;
        T = ((uint32_t)b0 << 21) | ((uint32_t)b1 << 10) | (uint32_t)b2;

        if (cC <= CAP_C) {
            for (int j = tid; j < cC; j += 256) {
                uint32_t v = Cu[j];
                if ((int)(v & 0x3FF) > b2) {
                    int p = atomicAdd(&s_cntA, 1);
                    if (p < 64) listA[p] = (int)Ci[j];
                }
            }
        } else {
            uint32_t pref = ((uint32_t)b0 << 11) | (uint32_t)b1;
            for (int i = tid; i < N_LAT; i += 256) {
                uint32_t v = sf[i];
                if ((v >> 10) != pref) continue;
                if ((int)(v & 0x3FF) > b2) {
                    int p = atomicAdd(&s_cntA, 1);
                    if (p < 64) listA[p] = i;
                }
            }
        }
        __syncthreads();

        int last = -1;
        for (int s = 0; s < Need; s++) {
            int loc = 0x7FFFFFFF;
            if (cC <= CAP_C) {
                for (int j = tid; j < cC; j += 256) {
                    if (Cu[j] == T) {
                        int ix = (int)Ci[j];
                        if (ix > last && ix < loc) loc = ix;
                    }
                }
            } else {
                for (int i = tid; i < N_LAT; i += 256) {
                    if (sf[i] == T && i > last && i < loc) loc = i;
                }
            }
            red[tid] = loc;
            __syncthreads();
            for (int st = 128; st > 0; st >>= 1) {
                if (tid < st) red[tid] = min(red[tid], red[tid + st]);
                __syncthreads();
            }
            if (tid == 0) { tiesel[s] = red[0]; s_last = red[0]; }
            __syncthreads();
            last = s_last;
        }
    }

    int cA = s_cntA;

    // ---- rank + write (descending value, ascending index on ties) ----
    if (tid < 64) {
        float v; int ix;
        if (tid < cA) { ix = listA[tid]; v = __uint_as_float(sf[ix]); }
        else          { ix = tiesel[tid - cA]; v = __uint_as_float(T); }
        pv[tid] = v; pi[tid] = ix;
    }
    __syncthreads();
    if (tid < 64) {
        float v = pv[tid]; int ix = pi[tid];
        int rank = 0;
        #pragma unroll 8
        for (int j = 0; j < 64; j++) {
            float vj = pv[j]; int ij = pi[j];
            if (vj > v || (vj == v && ij < ix)) rank++;
        }
        size_t o = (size_t)row * TOPK + rank;
        g_top_val[o] = v;
        g_top_idx[o] = ix;
        if (p_ta) p_ta[o] = v;
        if (p_ti) p_ti[o] = (float)ix;
    }
}

// ============================================================
__global__ void decode_kernel(const float* __restrict__ X,
                              const float* __restrict__ Wd,
                              const float* __restrict__ bdec,
                              float* __restrict__ sae)
{
    __shared__ float sval[64];
    __shared__ int   sidx[64];
    __shared__ float red[256];
    int tid = threadIdx.x, row = blockIdx.x;
    if (tid < 64) {
        sval[tid] = g_top_val[row * TOPK + tid];
        sidx[tid] = g_top_idx[row * TOPK + tid];
    }
    __syncthreads();
    int d0 = tid * 4;
    float4 acc = *(const float4*)(bdec + d0);
    #pragma unroll 4
    for (int k = 0; k < TOPK; k++) {
        float a = sval[k];
        float4 w = *(const float4*)(Wd + (size_t)sidx[k] * D_DIM + d0);
        acc.x += a * w.x; acc.y += a * w.y; acc.z += a * w.z; acc.w += a * w.w;
    }
    size_t o = (size_t)row * D_DIM + d0;
    if (sae) *(float4*)(sae + o) = acc;
    float4 xv = *(const float4*)(X + o);
    float ex = acc.x - xv.x, ey = acc.y - xv.y, ez = acc.z - xv.z, ew = acc.w - xv.w;
    red[tid] = ex * ex + ey * ey + ez * ez + ew * ew;
    __syncthreads();
    for (int st = 128; st > 0; st >>= 1) {
        if (tid < st) red[tid] += red[tid + st];
        __syncthreads();
    }
    if (tid == 0) atomicAdd(&g_acc[0], red[0]);
}

// ============================================================
__global__ void finalize_kernel(float* __restrict__ p_sc) {
    __shared__ float red[256];
    int tid = threadIdx.x;
    float s = 0.f;
    for (int i = tid; i < D_DIM; i += 256) {
        float cs = g_colsum[i];
        s += cs * cs;
    }
    red[tid] = s;
    __syncthreads();
    for (int st = 128; st > 0; st >>= 1) {
        if (tid < st) red[tid] += red[tid + st];
        __syncthreads();
    }
    if (tid == 0) {
        float TV  = g_acc[1] - red[0] / (float)B_N;
        float SSE = g_acc[0];
        p_sc[0] = SSE / TV;
        p_sc[1] = 0.f;
        p_sc[2] = 0.f;
        p_sc[3] = 0.f;
        p_sc[4] = SSE / (float)B_N;
    }
}

// ============================================================
extern "C" void kernel_launch(void* const* d_in, const int* in_sizes, int n_in,
                              void* d_out, int out_size)
{
    const float *x = nullptr, *We = nullptr, *be = nullptr, *Wd = nullptr, *bd = nullptr;
    int big_seen = 0;
    for (int i = 0; i < n_in; i++) {
        int sz = in_sizes[i];
        const float* p = (const float*)d_in[i];
        if (sz == (int)SZ_SAE)          x = p;
        else if (sz == N_LAT * D_DIM)   { if (big_seen++ == 0) We = p; else Wd = p; }
        else if (sz == N_LAT)           be = p;
        else if (sz == D_DIM)           bd = p;
    }

    float* out = (float*)d_out;
    float *p_sae = nullptr, *p_feat = nullptr, *p_ta = nullptr, *p_ti = nullptr, *p_sc = nullptr;

    if ((size_t)out_size == TOTAL_FULL) {
        p_sae  = out;
        p_feat = out + SZ_SAE;
        p_ta   = out + SZ_SAE + SZ_FEAT;
        p_ti   = p_ta + SZ_TA;
        p_sc   = p_ti + SZ_TA;
    } else if ((size_t)out_size == TOTAL_NOFEAT) {
        p_sae = out;
        p_ta  = out + SZ_SAE;
        p_ti  = p_ta + SZ_TA;
        p_sc  = p_ti + SZ_TA;
    } else {
        p_sae = out;
    }

    if (!p_feat) {
        void* fp = nullptr;
        cudaGetSymbolAddress(&fp, g_feat_fallback);
        p_feat = (float*)fp;
    }

    init_kernel<<<4, 256>>>();
    xc_colstats_kernel<<<dim3(4, 16), 256>>>(x, bd);
    cudaFuncSetAttribute(encode_gemm, cudaFuncAttributeMaxDynamicSharedMemorySize, 98304);
    encode_gemm<<<dim3(B_N / 256, N_LAT / 128), 512, 98304>>>(We, be, p_feat);
    cudaFuncSetAttribute(topk_kernel, cudaFuncAttributeMaxDynamicSharedMemorySize, TOPK_SMEM);
    topk_kernel<<<B_N, 256, TOPK_SMEM>>>(p_feat, p_ta, p_ti);
    decode_kernel<<<B_N, 256>>>(x, Wd, bd, p_sae);
    if (p_sc) finalize_kernel<<<1, 256>>>(p_sc);
}